// round 1
// baseline (speedup 1.0000x reference)
#include <cuda_runtime.h>
#include <math.h>

#define NB 4
#define LSEQ 4096
#define CC 512
#define C2 1024
#define HH 8
#define DD 64
#define ROWS (NB*LSEQ)          // 16384
#define SPLIT 16
#define SCHUNK (LSEQ/SPLIT)     // 256
#define NLAYERS 12

#define ELEMS (NB*LSEQ*CC)      // 8388608
#define ELEMS4 (ELEMS/4)        // 2097152

// ---------------- scratch (device globals; no allocation) ----------------
__device__ float g_f0[ELEMS];
__device__ float g_f1[ELEMS];
__device__ float g_q[ELEMS];
__device__ float g_k[ELEMS];
__device__ float g_v[ELEMS];
__device__ float g_m[ELEMS];
__device__ float g_cat[NB*LSEQ*C2];
__device__ float g_t[NB*LSEQ*C2];
__device__ float g_kvp[SPLIT*NB*HH*DD*DD];
__device__ float g_ksp[SPLIT*NB*HH*DD];
__device__ float g_kv[NB*HH*DD*DD];
__device__ float g_ksum[NB*HH*DD];

__device__ __forceinline__ float* buf(int s){
  switch(s){
    case 0: return g_f0; case 1: return g_f1; case 2: return g_q;
    case 3: return g_k;  case 4: return g_v;  case 5: return g_m;
    case 6: return g_cat; default: return g_t;
  }
}

// ---------------- SGEMM: C = epi(A[M,K] @ B[K,N]) ----------------
// 128x128 tile, BK=8, 256 threads, 8x8 per thread. M%128==0, N%128==0, K%8==0.
// EPI: 0 none, 1 elu(x)+1, 2 scale 1/4096, 3 relu
template<int EPI>
__global__ __launch_bounds__(256)
void sgemm(int Asel, const float* __restrict__ B, int Csel, int M, int N, int K)
{
  const float* A = buf(Asel);
  float* C = buf(Csel);
  __shared__ float As[8][132];   // transposed: As[k][m]
  __shared__ float Bs[8][132];
  const int bm = blockIdx.y * 128;
  const int bn = blockIdx.x * 128;
  const int t = threadIdx.x;
  const int tx = t & 15, ty = t >> 4;
  const int arow = t >> 1, ac4 = (t & 1) * 4;
  const int brow = t >> 5, bc4 = (t & 31) * 4;
  const float* Ap = A + (size_t)(bm + arow) * K + ac4;
  const float* Bp = B + (size_t)brow * N + bn + bc4;
  float acc[8][8] = {};
  for (int k0 = 0; k0 < K; k0 += 8) {
    float4 a = *(const float4*)(Ap + k0);
    As[ac4+0][arow] = a.x;
    As[ac4+1][arow] = a.y;
    As[ac4+2][arow] = a.z;
    As[ac4+3][arow] = a.w;
    *(float4*)&Bs[brow][bc4] = *(const float4*)(Bp + (size_t)k0 * N);
    __syncthreads();
#pragma unroll
    for (int kk = 0; kk < 8; kk++) {
      float4 a0 = *(const float4*)&As[kk][ty*8];
      float4 a1 = *(const float4*)&As[kk][ty*8+4];
      float4 b0 = *(const float4*)&Bs[kk][tx*8];
      float4 b1 = *(const float4*)&Bs[kk][tx*8+4];
      float ar[8] = {a0.x,a0.y,a0.z,a0.w,a1.x,a1.y,a1.z,a1.w};
      float br[8] = {b0.x,b0.y,b0.z,b0.w,b1.x,b1.y,b1.z,b1.w};
#pragma unroll
      for (int i=0;i<8;i++)
#pragma unroll
        for (int j=0;j<8;j++)
          acc[i][j] = fmaf(ar[i], br[j], acc[i][j]);
    }
    __syncthreads();
  }
#pragma unroll
  for (int i=0;i<8;i++){
    float* crow = C + (size_t)(bm + ty*8 + i) * N + bn + tx*8;
#pragma unroll
    for (int j=0;j<8;j++){
      float v = acc[i][j];
      if (EPI==1) v = (v > 0.f) ? (v + 1.f) : expf(v);
      else if (EPI==2) v *= (1.0f/4096.0f);
      else if (EPI==3) v = (v > 0.f) ? v : 0.f;
      acc[i][j] = v;
    }
    *(float4*)crow     = make_float4(acc[i][0],acc[i][1],acc[i][2],acc[i][3]);
    *(float4*)(crow+4) = make_float4(acc[i][4],acc[i][5],acc[i][6],acc[i][7]);
  }
}

// ---------------- KV aggregation: split-K partials (deterministic) ----------------
// grid (SPLIT, NB*HH), 256 threads. acc[d][e] += K[s,d]*V[s,e]; ksum[d] += K[s,d]
__global__ __launch_bounds__(256)
void kv_partial()
{
  const int nh = blockIdx.y, part = blockIdx.x;
  const int n = nh >> 3, h = nh & 7;
  __shared__ float Ks[32][68];
  __shared__ float Vs[32][68];
  const int t = threadIdx.x;
  const int tx = t & 15, ty = t >> 4;
  const float* Kb = g_k + (size_t)n*LSEQ*CC + h*DD;
  const float* Vb = g_v + (size_t)n*LSEQ*CC + h*DD;
  float acc[4][4] = {};
  float ksum = 0.f;
  const int send = part*SCHUNK + SCHUNK;
  for (int s0 = part*SCHUNK; s0 < send; s0 += 32) {
#pragma unroll
    for (int p=0;p<2;p++){
      int idx = t + p*256;
      int r = idx >> 4, c4 = (idx & 15) << 2;
      *(float4*)&Ks[r][c4] = *(const float4*)(Kb + (size_t)(s0+r)*CC + c4);
      *(float4*)&Vs[r][c4] = *(const float4*)(Vb + (size_t)(s0+r)*CC + c4);
    }
    __syncthreads();
    if (t < DD){
#pragma unroll
      for (int kk=0;kk<32;kk++) ksum += Ks[kk][t];
    }
#pragma unroll
    for (int kk=0;kk<32;kk++){
      float4 a = *(const float4*)&Ks[kk][ty*4];
      float4 b = *(const float4*)&Vs[kk][tx*4];
      float ar[4]={a.x,a.y,a.z,a.w}, br[4]={b.x,b.y,b.z,b.w};
#pragma unroll
      for (int i=0;i<4;i++)
#pragma unroll
        for (int j=0;j<4;j++) acc[i][j] = fmaf(ar[i],br[j],acc[i][j]);
    }
    __syncthreads();
  }
  float* dst = g_kvp + ((size_t)part*NB*HH + nh)*DD*DD;
#pragma unroll
  for (int i=0;i<4;i++)
    *(float4*)&dst[(ty*4+i)*DD + tx*4] =
        make_float4(acc[i][0],acc[i][1],acc[i][2],acc[i][3]);
  if (t < DD) g_ksp[(size_t)part*NB*HH*DD + nh*DD + t] = ksum;
}

__global__ __launch_bounds__(256)
void kv_reduce()
{
  int i = blockIdx.x*256 + threadIdx.x;
  if (i < NB*HH*DD*DD){
    float s = 0.f;
#pragma unroll
    for (int p=0;p<SPLIT;p++) s += g_kvp[(size_t)p*NB*HH*DD*DD + i];
    g_kv[i] = s;
  }
  if (i < NB*HH*DD){
    float s=0.f;
#pragma unroll
    for (int p=0;p<SPLIT;p++) s += g_ksp[p*NB*HH*DD + i];
    g_ksum[i] = s;
  }
}

// ---------------- msg: per (n,h), tile of 64 rows: msg = (Q @ KV) * S/(Q.Ksum+eps) ----------------
__global__ __launch_bounds__(256)
void msg_kernel()
{
  const int nh = blockIdx.y;
  const int n = nh >> 3, h = nh & 7;
  const int l0 = blockIdx.x * 64;
  __shared__ float Qs[64][68];    // transposed: Qs[d][m]
  __shared__ float KVs[64][68];   // KVs[d][e]
  __shared__ float ksm[64];
  __shared__ float zrow[64];
  const int t = threadIdx.x;
  const int tx = t & 15, ty = t >> 4;
  const float* Qb  = g_q  + (size_t)n*LSEQ*CC + h*DD;
  const float* KVb = g_kv + (size_t)nh*DD*DD;
#pragma unroll
  for (int p=0;p<4;p++){
    int idx = t + p*256;
    int r = idx >> 4, c4 = (idx & 15) << 2;
    float4 q = *(const float4*)(Qb + (size_t)(l0+r)*CC + c4);
    Qs[c4+0][r]=q.x; Qs[c4+1][r]=q.y; Qs[c4+2][r]=q.z; Qs[c4+3][r]=q.w;
    *(float4*)&KVs[r][c4] = *(const float4*)(KVb + r*DD + c4);
  }
  if (t < DD) ksm[t] = g_ksum[nh*DD + t];
  __syncthreads();
  if (t < DD){
    float dn = 0.f;
#pragma unroll
    for (int d=0; d<DD; d++) dn = fmaf(Qs[d][t], ksm[d], dn);
    zrow[t] = 4096.0f / (dn + 1e-6f);
  }
  __syncthreads();
  float acc[4][4] = {};
#pragma unroll
  for (int kk=0; kk<DD; kk++){
    float4 a = *(const float4*)&Qs[kk][ty*4];
    float4 b = *(const float4*)&KVs[kk][tx*4];
    float ar[4]={a.x,a.y,a.z,a.w}, br[4]={b.x,b.y,b.z,b.w};
#pragma unroll
    for (int i=0;i<4;i++)
#pragma unroll
      for (int j=0;j<4;j++) acc[i][j] = fmaf(ar[i],br[j],acc[i][j]);
  }
  float* Ob = g_m + (size_t)n*LSEQ*CC + h*DD;
#pragma unroll
  for (int i=0;i<4;i++){
    int m = ty*4+i;
    float z = zrow[m];
    *(float4*)(Ob + (size_t)(l0+m)*CC + tx*4) =
        make_float4(acc[i][0]*z, acc[i][1]*z, acc[i][2]*z, acc[i][3]*z);
  }
}

// ---------------- LayerNorm (optionally + residual), C=512, 128 threads/row ----------------
__global__ __launch_bounds__(128)
void ln_kernel(int insel, const float* __restrict__ gamma, const float* __restrict__ beta,
               int outsel, int out_off, int out_stride, int resel)
{
  const float* in = buf(insel);
  float* out = buf(outsel);
  const int row = blockIdx.x;
  const int t = threadIdx.x;
  float4 v = *(const float4*)(in + (size_t)row*CC + t*4);
  float s  = v.x+v.y+v.z+v.w;
  float s2 = v.x*v.x + v.y*v.y + v.z*v.z + v.w*v.w;
  __shared__ float sh[8];
#pragma unroll
  for (int o=16;o>0;o>>=1){
    s  += __shfl_xor_sync(0xffffffffu, s, o);
    s2 += __shfl_xor_sync(0xffffffffu, s2, o);
  }
  if ((t & 31) == 0){ sh[t>>5] = s; sh[4 + (t>>5)] = s2; }
  __syncthreads();
  s  = sh[0]+sh[1]+sh[2]+sh[3];
  s2 = sh[4]+sh[5]+sh[6]+sh[7];
  const float mu  = s * (1.0f/CC);
  const float var = s2 * (1.0f/CC) - mu*mu;
  const float rs  = rsqrtf(var + 1e-5f);
  float4 g = *(const float4*)(gamma + t*4);
  float4 b = *(const float4*)(beta + t*4);
  float4 o;
  o.x = (v.x-mu)*rs*g.x + b.x;
  o.y = (v.y-mu)*rs*g.y + b.y;
  o.z = (v.z-mu)*rs*g.z + b.z;
  o.w = (v.w-mu)*rs*g.w + b.w;
  if (resel >= 0){
    const float* res = buf(resel);
    float4 r = *(const float4*)(res + (size_t)row*CC + t*4);
    o.x += r.x; o.y += r.y; o.z += r.z; o.w += r.w;
  }
  *(float4*)(out + (size_t)row*out_stride + out_off + t*4) = o;
}

// ---------------- concat first half: g_cat[:, :512] = x ----------------
__global__ __launch_bounds__(256)
void cat_copy(int xsel)
{
  const float* x = buf(xsel);
  int i = blockIdx.x*256 + threadIdx.x;     // over ROWS*128 float4s
  int row = i >> 7, c4 = i & 127;
  *(float4*)(g_cat + (size_t)row*C2 + c4*4) =
      *(const float4*)(x + (size_t)row*CC + c4*4);
}

__global__ __launch_bounds__(256)
void copy_in(const float* __restrict__ f0, const float* __restrict__ f1)
{
  size_t i = (size_t)blockIdx.x*256 + threadIdx.x;
  ((float4*)g_f0)[i] = ((const float4*)f0)[i];
  ((float4*)g_f1)[i] = ((const float4*)f1)[i];
}

__global__ __launch_bounds__(256)
void copy_out(float* __restrict__ out)
{
  size_t i = (size_t)blockIdx.x*256 + threadIdx.x;
  ((float4*)out)[i]          = ((const float4*)g_f0)[i];
  ((float4*)out)[i + ELEMS4] = ((const float4*)g_f1)[i];
}

// ---------------- host-side layer driver ----------------
static void enc_layer(int xsel, int ssel,
                      const float* Wq, const float* Wk, const float* Wv, const float* Wm,
                      const float* W1, const float* W2,
                      const float* gg1, const float* bb1,
                      const float* gg2, const float* bb2)
{
  dim3 blk(256);
  dim3 gC (CC/128, ROWS/128);    // (4,128)
  dim3 gC2(C2/128, ROWS/128);    // (8,128)
  sgemm<1><<<gC, blk>>>(xsel, Wq, 2, ROWS, CC, CC);                 // Q = elu(x@Wq)+1
  sgemm<1><<<gC, blk>>>(ssel, Wk, 3, ROWS, CC, CC);                 // K = elu(src@Wk)+1
  sgemm<2><<<gC, blk>>>(ssel, Wv, 4, ROWS, CC, CC);                 // V = (src@Wv)/S
  kv_partial<<<dim3(SPLIT, NB*HH), blk>>>();
  kv_reduce<<<512, 256>>>();
  msg_kernel<<<dim3(LSEQ/64, NB*HH), blk>>>();                      // g_m
  sgemm<0><<<gC, blk>>>(5, Wm, 2, ROWS, CC, CC);                    // g_q = msg@Wm
  cat_copy<<<ELEMS4/256, blk>>>(xsel);                              // cat[:, :C] = x
  ln_kernel<<<ROWS,128>>>(2, gg1, bb1, 6, CC, C2, -1);              // cat[:, C:] = LN1(msg@Wm)
  sgemm<3><<<gC2, blk>>>(6, W1, 7, ROWS, C2, C2);                   // g_t = relu(cat@W1)
  sgemm<0><<<gC, blk>>>(7, W2, 3, ROWS, CC, C2);                    // g_k = g_t@W2
  ln_kernel<<<ROWS,128>>>(3, gg2, bb2, xsel, 0, CC, xsel);          // x = x + LN2(.)
}

extern "C" void kernel_launch(void* const* d_in, const int* in_sizes, int n_in,
                              void* d_out, int out_size)
{
  (void)in_sizes; (void)n_in; (void)out_size;
  const float* feat0 = (const float*)d_in[0];
  const float* feat1 = (const float*)d_in[1];
  const float* Wq = (const float*)d_in[2];
  const float* Wk = (const float*)d_in[3];
  const float* Wv = (const float*)d_in[4];
  const float* Wm = (const float*)d_in[5];
  const float* W1 = (const float*)d_in[6];
  const float* W2 = (const float*)d_in[7];
  const float* g1 = (const float*)d_in[8];
  const float* b1 = (const float*)d_in[9];
  const float* g2 = (const float*)d_in[10];
  const float* b2 = (const float*)d_in[11];

  copy_in<<<ELEMS4/256, 256>>>(feat0, feat1);

  for (int i = 0; i < NLAYERS; i++){
    const float* wq  = Wq + (size_t)i*CC*CC;
    const float* wk  = Wk + (size_t)i*CC*CC;
    const float* wv  = Wv + (size_t)i*CC*CC;
    const float* wm  = Wm + (size_t)i*CC*CC;
    const float* w1  = W1 + (size_t)i*C2*C2;
    const float* w2  = W2 + (size_t)i*C2*CC;
    const float* gg1 = g1 + (size_t)i*CC;
    const float* bb1 = b1 + (size_t)i*CC;
    const float* gg2 = g2 + (size_t)i*CC;
    const float* bb2 = b2 + (size_t)i*CC;
    if ((i & 1) == 0){  // self
      enc_layer(0, 0, wq,wk,wv,wm,w1,w2,gg1,bb1,gg2,bb2);
      enc_layer(1, 1, wq,wk,wv,wm,w1,w2,gg1,bb1,gg2,bb2);
    } else {            // cross (sequential: feat1 sees updated feat0)
      enc_layer(0, 1, wq,wk,wv,wm,w1,w2,gg1,bb1,gg2,bb2);
      enc_layer(1, 0, wq,wk,wv,wm,w1,w2,gg1,bb1,gg2,bb2);
    }
  }

  copy_out<<<ELEMS4/256, 256>>>((float*)d_out);
}

// round 3
// speedup vs baseline: 2.9534x; 2.9534x over previous
#include <cuda_runtime.h>
#include <cuda_bf16.h>
#include <math.h>
#include <stdint.h>

#define NB 4
#define LSEQ 4096
#define CC 512
#define C2 1024
#define HH 8
#define DD 64
#define ROWS (NB*LSEQ)          // 16384
#define SPLIT 16
#define SCHUNK (LSEQ/SPLIT)     // 256
#define NLAYERS 12
#define ELEMS (ROWS*CC)         // 8388608
#define ELEMS4 (ELEMS/4)

typedef __nv_bfloat16 bf16;

// ---------------- device globals (no allocation) ----------------
__device__ float g_f0[ELEMS], g_f1[ELEMS];
__device__ float g_q[ELEMS], g_k[ELEMS], g_v[ELEMS], g_m[ELEMS];
__device__ float g_kvp[SPLIT*NB*HH*DD*DD];
__device__ float g_ksp[SPLIT*NB*HH*DD];
__device__ float g_kv[NB*HH*DD*DD];
__device__ float g_ksum[NB*HH*DD];

// bf16 hi/lo activation shadows
__device__ bf16 s_xh0[ELEMS], s_xl0[ELEMS], s_xh1[ELEMS], s_xl1[ELEMS];
__device__ bf16 s_mh[ELEMS],  s_ml[ELEMS];
__device__ bf16 s_ch[ROWS*C2], s_cl[ROWS*C2];
__device__ bf16 s_th[ROWS*C2], s_tl[ROWS*C2];

// transposed bf16 hi/lo weights: [N rows][K cols], per layer
__device__ bf16 w_qh[NLAYERS*CC*CC], w_ql[NLAYERS*CC*CC];
__device__ bf16 w_kh[NLAYERS*CC*CC], w_kl[NLAYERS*CC*CC];
__device__ bf16 w_vh[NLAYERS*CC*CC], w_vl[NLAYERS*CC*CC];
__device__ bf16 w_mh[NLAYERS*CC*CC], w_ml[NLAYERS*CC*CC];
__device__ bf16 w_1h[NLAYERS*C2*C2], w_1l[NLAYERS*C2*C2];
__device__ bf16 w_2h[NLAYERS*CC*C2], w_2l[NLAYERS*CC*C2];

// ---------------- helpers ----------------
__device__ __forceinline__ uint32_t s2u(const void* p){
  uint32_t a;
  asm("{ .reg .u64 t; cvta.to.shared.u64 t, %1; cvt.u32.u64 %0, t; }" : "=r"(a) : "l"(p));
  return a;
}

__device__ __forceinline__ void split_store4(bf16* H, bf16* L, size_t idx,
                                             float a, float b, float c, float d){
  bf16 h0=__float2bfloat16(a), h1=__float2bfloat16(b),
       h2=__float2bfloat16(c), h3=__float2bfloat16(d);
  bf16 l0=__float2bfloat16(a-__bfloat162float(h0));
  bf16 l1=__float2bfloat16(b-__bfloat162float(h1));
  bf16 l2=__float2bfloat16(c-__bfloat162float(h2));
  bf16 l3=__float2bfloat16(d-__bfloat162float(h3));
  *(ushort4*)(H+idx) = make_ushort4(__bfloat16_as_ushort(h0), __bfloat16_as_ushort(h1),
                                    __bfloat16_as_ushort(h2), __bfloat16_as_ushort(h3));
  *(ushort4*)(L+idx) = make_ushort4(__bfloat16_as_ushort(l0), __bfloat16_as_ushort(l1),
                                    __bfloat16_as_ushort(l2), __bfloat16_as_ushort(l3));
}

__device__ __forceinline__ void split_store2(bf16* H, bf16* L, size_t idx, float a, float b){
  bf16 h0=__float2bfloat16(a), h1=__float2bfloat16(b);
  bf16 l0=__float2bfloat16(a-__bfloat162float(h0));
  bf16 l1=__float2bfloat16(b-__bfloat162float(h1));
  *(ushort2*)(H+idx) = make_ushort2(__bfloat16_as_ushort(h0), __bfloat16_as_ushort(h1));
  *(ushort2*)(L+idx) = make_ushort2(__bfloat16_as_ushort(l0), __bfloat16_as_ushort(l1));
}

__device__ __forceinline__ void cpasync16(uint32_t dst, const void* src){
  asm volatile("cp.async.cg.shared.global [%0], [%1], 16;" :: "r"(dst), "l"(src));
}

__device__ __forceinline__ void ldsm4(uint32_t* r, uint32_t addr){
  asm volatile("ldmatrix.sync.aligned.m8n8.x4.shared.b16 {%0,%1,%2,%3}, [%4];"
    : "=r"(r[0]),"=r"(r[1]),"=r"(r[2]),"=r"(r[3]) : "r"(addr));
}

__device__ __forceinline__ void mma16816(float* d, const uint32_t* a, const uint32_t* b){
  asm volatile("mma.sync.aligned.m16n8k16.row.col.f32.bf16.bf16.f32 "
    "{%0,%1,%2,%3},{%4,%5,%6,%7},{%8,%9},{%0,%1,%2,%3};"
    : "+f"(d[0]),"+f"(d[1]),"+f"(d[2]),"+f"(d[3])
    : "r"(a[0]),"r"(a[1]),"r"(a[2]),"r"(a[3]), "r"(b[0]),"r"(b[1]));
}

// swizzled byte offset within an 8KB tile (128 rows x 32 bf16; 2 rows per 128B physrow)
__device__ __forceinline__ uint32_t swoff(int row, int c){
  int pr = row >> 1;
  int ch = ((row & 1)*4 + c) ^ (pr & 7);
  return (uint32_t)(pr*128 + ch*16);
}

// ---------------- operand selectors ----------------
__device__ __forceinline__ void apair(int s, const bf16*& h, const bf16*& l){
  switch(s){
    case 0: h=s_xh0; l=s_xl0; break;
    case 1: h=s_xh1; l=s_xl1; break;
    case 2: h=s_mh;  l=s_ml;  break;
    case 3: h=s_ch;  l=s_cl;  break;
    default:h=s_th;  l=s_tl;  break;
  }
}
__device__ __forceinline__ void bpair(int s, int layer, const bf16*& h, const bf16*& l){
  size_t o;
  switch(s){
    case 0: o=(size_t)layer*CC*CC; h=w_qh+o; l=w_ql+o; break;
    case 1: o=(size_t)layer*CC*CC; h=w_kh+o; l=w_kl+o; break;
    case 2: o=(size_t)layer*CC*CC; h=w_vh+o; l=w_vl+o; break;
    case 3: o=(size_t)layer*CC*CC; h=w_mh+o; l=w_ml+o; break;
    case 4: o=(size_t)layer*C2*C2; h=w_1h+o; l=w_1l+o; break;
    default:o=(size_t)layer*CC*C2; h=w_2h+o; l=w_2l+o; break;
  }
}
__device__ __forceinline__ float* cbuf(int s){
  switch(s){ case 0: return g_q; case 1: return g_k; case 2: return g_v; default: return g_m; }
}

// ---------------- split-bf16 GEMM via mma.sync (HMMA) ----------------
// C[M,N] = epi( (Ahi+Alo)[M,K] @ (Bhi+Blo)^T[N,K] ), 128x128x32 CTA tile, 3-stage cp.async.
// EPI: 0 none->fp32, 1 elu+1->fp32, 2 /4096->fp32, 3 relu->bf16 hi/lo (t buffers)
#define NSTG 3
#define STG_BYTES 32768
#define MMA_SMEM (NSTG*STG_BYTES)

template<int EPI>
__global__ __launch_bounds__(256)
void mma_gemm(int Asel, int Bsel, int layer, int Csel, int N, int K)
{
  extern __shared__ char smc[];
  const uint32_t sb = s2u(smc);

  const bf16 *Ah,*Al,*Bh,*Bl;
  apair(Asel, Ah, Al);
  bpair(Bsel, layer, Bh, Bl);

  const int t = threadIdx.x, lane = t & 31, wid = t >> 5;
  const int wm = wid & 1, wn = wid >> 1;       // warp tile 64x32
  const int bm = blockIdx.y*128, bn = blockIdx.x*128;
  const int nc = K >> 5;

  const bf16* gsrc[4];
  gsrc[0] = Ah + (size_t)bm*K;
  gsrc[1] = Al + (size_t)bm*K;
  gsrc[2] = Bh + (size_t)bn*K;
  gsrc[3] = Bl + (size_t)bn*K;

  const int lr0 = t >> 2, lc0 = t & 3;         // 16B unit coords (row, chunk)

  // ldmatrix lane decomposition
  const int lm = lane >> 3, lrr = lane & 7;

  float acc[4][4][4];
#pragma unroll
  for (int i=0;i<4;i++)
#pragma unroll
    for (int j=0;j<4;j++)
#pragma unroll
      for (int q=0;q<4;q++) acc[i][j][q] = 0.f;

#define LOAD_STAGE(stg, ck) do {                                              \
    uint32_t base_ = sb + (stg)*STG_BYTES;                                    \
    int k0_ = (ck)*32;                                                        \
    _Pragma("unroll")                                                         \
    for (int tl_=0; tl_<4; tl_++){                                            \
      uint32_t tb_ = base_ + tl_*8192;                                        \
      const char* g_ = (const char*)(gsrc[tl_] + k0_);                        \
      cpasync16(tb_ + swoff(lr0,    lc0), g_ + ((size_t)lr0   *K + lc0*8)*2); \
      cpasync16(tb_ + swoff(lr0+64, lc0), g_ + ((size_t)(lr0+64)*K + lc0*8)*2);\
    }                                                                         \
    asm volatile("cp.async.commit_group;");                                   \
  } while(0)

  LOAD_STAGE(0, 0);
  LOAD_STAGE(1, 1);          // nc >= 16 always

  for (int c = 0; c < nc; c++){
    if (c + 2 < nc) LOAD_STAGE((c+2)%NSTG, c+2);
    int rem = nc - 1 - c;
    if (rem >= 2)      asm volatile("cp.async.wait_group 2;" ::: "memory");
    else if (rem == 1) asm volatile("cp.async.wait_group 1;" ::: "memory");
    else               asm volatile("cp.async.wait_group 0;" ::: "memory");
    __syncthreads();

    const uint32_t base = sb + (c%NSTG)*STG_BYTES;
#pragma unroll
    for (int k16 = 0; k16 < 2; k16++){
      uint32_t ah[4][4], al[4][4], bh[4][2], bl[4][2];
#pragma unroll
      for (int mt = 0; mt < 4; mt++){
        int row = wm*64 + mt*16 + (lm&1)*8 + lrr;
        int ch  = k16*2 + (lm>>1);
        uint32_t o = swoff(row, ch);
        ldsm4(ah[mt], base + o);
        ldsm4(al[mt], base + 8192 + o);
      }
#pragma unroll
      for (int g = 0; g < 2; g++){
        int row = wn*32 + g*16 + (lm>>1)*8 + lrr;
        int ch  = k16*2 + (lm&1);
        uint32_t o = swoff(row, ch);
        uint32_t r4[4];
        ldsm4(r4, base + 16384 + o);
        bh[g*2][0]=r4[0]; bh[g*2][1]=r4[1]; bh[g*2+1][0]=r4[2]; bh[g*2+1][1]=r4[3];
        ldsm4(r4, base + 24576 + o);
        bl[g*2][0]=r4[0]; bl[g*2][1]=r4[1]; bl[g*2+1][0]=r4[2]; bl[g*2+1][1]=r4[3];
      }
#pragma unroll
      for (int mt = 0; mt < 4; mt++)
#pragma unroll
        for (int nt = 0; nt < 4; nt++){
          mma16816(acc[mt][nt], ah[mt], bh[nt]);
          mma16816(acc[mt][nt], al[mt], bh[nt]);
          mma16816(acc[mt][nt], ah[mt], bl[nt]);
        }
    }
    __syncthreads();
  }

  // ---------------- epilogue ----------------
  const int er = bm + wm*64 + (lane>>2);
  const int ec = bn + wn*32 + 2*(lane&3);
#pragma unroll
  for (int mt = 0; mt < 4; mt++){
#pragma unroll
    for (int nt = 0; nt < 4; nt++){
      int row = er + mt*16;
      int col = ec + nt*8;
      float v0 = acc[mt][nt][0], v1 = acc[mt][nt][1];
      float v2 = acc[mt][nt][2], v3 = acc[mt][nt][3];
      if (EPI == 1){
        v0 = v0 > 0.f ? v0 + 1.f : expf(v0);
        v1 = v1 > 0.f ? v1 + 1.f : expf(v1);
        v2 = v2 > 0.f ? v2 + 1.f : expf(v2);
        v3 = v3 > 0.f ? v3 + 1.f : expf(v3);
      } else if (EPI == 2){
        v0 *= (1.f/4096.f); v1 *= (1.f/4096.f);
        v2 *= (1.f/4096.f); v3 *= (1.f/4096.f);
      } else if (EPI == 3){
        v0 = v0 > 0.f ? v0 : 0.f; v1 = v1 > 0.f ? v1 : 0.f;
        v2 = v2 > 0.f ? v2 : 0.f; v3 = v3 > 0.f ? v3 : 0.f;
      }
      if (EPI == 3){
        split_store2(s_th, s_tl, (size_t)row*N + col, v0, v1);
        split_store2(s_th, s_tl, (size_t)(row+8)*N + col, v2, v3);
      } else {
        float* C = cbuf(Csel);
        *(float2*)(C + (size_t)row*N + col)     = make_float2(v0, v1);
        *(float2*)(C + (size_t)(row+8)*N + col) = make_float2(v2, v3);
      }
    }
  }
}

// ---------------- weight prep: transpose + bf16 hi/lo split ----------------
__global__ __launch_bounds__(256)
void wprep(const float* __restrict__ W, int wsel, int K, int N)
{
  bf16 *oh, *ol;
  switch(wsel){
    case 0: oh=w_qh; ol=w_ql; break;
    case 1: oh=w_kh; ol=w_kl; break;
    case 2: oh=w_vh; ol=w_vl; break;
    case 3: oh=w_mh; ol=w_ml; break;
    case 4: oh=w_1h; ol=w_1l; break;
    default:oh=w_2h; ol=w_2l; break;
  }
  const int l = blockIdx.z;
  const float* Wl = W + (size_t)l*K*N;
  oh += (size_t)l*(size_t)N*K;
  ol += (size_t)l*(size_t)N*K;
  __shared__ float tile[32][33];
  const int k0 = blockIdx.y*32, n0 = blockIdx.x*32;
  const int tx = threadIdx.x, ty = threadIdx.y;
#pragma unroll
  for (int i = 0; i < 4; i++){
    int r = ty + i*8;
    tile[r][tx] = Wl[(size_t)(k0+r)*N + n0 + tx];
  }
  __syncthreads();
#pragma unroll
  for (int i = 0; i < 4; i++){
    int r = ty + i*8;
    float v = tile[tx][r];
    bf16 h = __float2bfloat16(v);
    bf16 lo = __float2bfloat16(v - __bfloat162float(h));
    oh[(size_t)(n0+r)*K + k0 + tx] = h;
    ol[(size_t)(n0+r)*K + k0 + tx] = lo;
  }
}

// ---------------- attention: KV split-K (deterministic) ----------------
__global__ __launch_bounds__(256)
void kv_partial()
{
  const int nh = blockIdx.y, part = blockIdx.x;
  const int n = nh >> 3, h = nh & 7;
  __shared__ float Ks[32][68];
  __shared__ float Vs[32][68];
  const int t = threadIdx.x;
  const int tx = t & 15, ty = t >> 4;
  const float* Kb = g_k + (size_t)n*LSEQ*CC + h*DD;
  const float* Vb = g_v + (size_t)n*LSEQ*CC + h*DD;
  float acc[4][4] = {};
  float ksum = 0.f;
  const int send = part*SCHUNK + SCHUNK;
  for (int s0 = part*SCHUNK; s0 < send; s0 += 32){
#pragma unroll
    for (int p = 0; p < 2; p++){
      int idx = t + p*256;
      int r = idx >> 4, c4 = (idx & 15) << 2;
      *(float4*)&Ks[r][c4] = *(const float4*)(Kb + (size_t)(s0+r)*CC + c4);
      *(float4*)&Vs[r][c4] = *(const float4*)(Vb + (size_t)(s0+r)*CC + c4);
    }
    __syncthreads();
    if (t < DD){
#pragma unroll
      for (int kk = 0; kk < 32; kk++) ksum += Ks[kk][t];
    }
#pragma unroll
    for (int kk = 0; kk < 32; kk++){
      float4 a = *(const float4*)&Ks[kk][ty*4];
      float4 b = *(const float4*)&Vs[kk][tx*4];
      float ar[4]={a.x,a.y,a.z,a.w}, br[4]={b.x,b.y,b.z,b.w};
#pragma unroll
      for (int i=0;i<4;i++)
#pragma unroll
        for (int j=0;j<4;j++) acc[i][j] = fmaf(ar[i],br[j],acc[i][j]);
    }
    __syncthreads();
  }
  float* dst = g_kvp + ((size_t)part*NB*HH + nh)*DD*DD;
#pragma unroll
  for (int i=0;i<4;i++)
    *(float4*)&dst[(ty*4+i)*DD + tx*4] =
        make_float4(acc[i][0],acc[i][1],acc[i][2],acc[i][3]);
  if (t < DD) g_ksp[(size_t)part*NB*HH*DD + nh*DD + t] = ksum;
}

__global__ __launch_bounds__(256)
void kv_reduce()
{
  int i = blockIdx.x*256 + threadIdx.x;
  if (i < NB*HH*DD*DD){
    float s = 0.f;
#pragma unroll
    for (int p=0;p<SPLIT;p++) s += g_kvp[(size_t)p*NB*HH*DD*DD + i];
    g_kv[i] = s;
  }
  if (i < NB*HH*DD){
    float s=0.f;
#pragma unroll
    for (int p=0;p<SPLIT;p++) s += g_ksp[p*NB*HH*DD + i];
    g_ksum[i] = s;
  }
}

// msg = (Q @ KV) * S/(Q.Ksum+eps)  -> bf16 hi/lo pair
__global__ __launch_bounds__(256)
void msg_kernel()
{
  const int nh = blockIdx.y;
  const int n = nh >> 3, h = nh & 7;
  const int l0 = blockIdx.x * 64;
  __shared__ float Qs[64][68];
  __shared__ float KVs[64][68];
  __shared__ float ksm[64];
  __shared__ float zrow[64];
  const int t = threadIdx.x;
  const int tx = t & 15, ty = t >> 4;
  const float* Qb  = g_q  + (size_t)n*LSEQ*CC + h*DD;
  const float* KVb = g_kv + (size_t)nh*DD*DD;
#pragma unroll
  for (int p=0;p<4;p++){
    int idx = t + p*256;
    int r = idx >> 4, c4 = (idx & 15) << 2;
    float4 q = *(const float4*)(Qb + (size_t)(l0+r)*CC + c4);
    Qs[c4+0][r]=q.x; Qs[c4+1][r]=q.y; Qs[c4+2][r]=q.z; Qs[c4+3][r]=q.w;
    *(float4*)&KVs[r][c4] = *(const float4*)(KVb + r*DD + c4);
  }
  if (t < DD) ksm[t] = g_ksum[nh*DD + t];
  __syncthreads();
  if (t < DD){
    float dn = 0.f;
#pragma unroll
    for (int d=0; d<DD; d++) dn = fmaf(Qs[d][t], ksm[d], dn);
    zrow[t] = 4096.0f / (dn + 1e-6f);
  }
  __syncthreads();
  float acc[4][4] = {};
#pragma unroll
  for (int kk=0; kk<DD; kk++){
    float4 a = *(const float4*)&Qs[kk][ty*4];
    float4 b = *(const float4*)&KVs[kk][tx*4];
    float ar[4]={a.x,a.y,a.z,a.w}, br[4]={b.x,b.y,b.z,b.w};
#pragma unroll
    for (int i=0;i<4;i++)
#pragma unroll
      for (int j=0;j<4;j++) acc[i][j] = fmaf(ar[i],br[j],acc[i][j]);
  }
#pragma unroll
  for (int i=0;i<4;i++){
    int m = ty*4+i;
    float z = zrow[m];
    size_t base = ((size_t)(n*LSEQ + l0 + m))*CC + h*DD + tx*4;
    split_store4(s_mh, s_ml, base, acc[i][0]*z, acc[i][1]*z, acc[i][2]*z, acc[i][3]*z);
  }
}

// ---------------- LN kernels ----------------
__device__ __forceinline__ void ln_core(const float4& v, int t, float& mu, float& rs)
{
  float s  = v.x+v.y+v.z+v.w;
  float s2 = v.x*v.x + v.y*v.y + v.z*v.z + v.w*v.w;
  __shared__ float sh[8];
#pragma unroll
  for (int o=16;o>0;o>>=1){
    s  += __shfl_xor_sync(0xffffffffu, s, o);
    s2 += __shfl_xor_sync(0xffffffffu, s2, o);
  }
  if ((t & 31) == 0){ sh[t>>5] = s; sh[4 + (t>>5)] = s2; }
  __syncthreads();
  s  = sh[0]+sh[1]+sh[2]+sh[3];
  s2 = sh[4]+sh[5]+sh[6]+sh[7];
  mu = s * (1.0f/CC);
  float var = s2 * (1.0f/CC) - mu*mu;
  rs = rsqrtf(var + 1e-5f);
}

__global__ __launch_bounds__(128)
void ln_to_cat(const float* __restrict__ gamma, const float* __restrict__ beta)
{
  const int row = blockIdx.x;
  const int t = threadIdx.x;
  float4 v = *(const float4*)(g_m + (size_t)row*CC + t*4);
  float mu, rs;
  ln_core(v, t, mu, rs);
  float4 g = *(const float4*)(gamma + t*4);
  float4 b = *(const float4*)(beta + t*4);
  float o0 = (v.x-mu)*rs*g.x + b.x;
  float o1 = (v.y-mu)*rs*g.y + b.y;
  float o2 = (v.z-mu)*rs*g.z + b.z;
  float o3 = (v.w-mu)*rs*g.w + b.w;
  split_store4(s_ch, s_cl, (size_t)row*C2 + CC + t*4, o0, o1, o2, o3);
}

__global__ __launch_bounds__(128)
void ln_res(int xsel, const float* __restrict__ gamma, const float* __restrict__ beta)
{
  const int row = blockIdx.x;
  const int t = threadIdx.x;
  float4 v = *(const float4*)(g_k + (size_t)row*CC + t*4);
  float mu, rs;
  ln_core(v, t, mu, rs);
  float4 g = *(const float4*)(gamma + t*4);
  float4 b = *(const float4*)(beta + t*4);
  float* x = xsel ? g_f1 : g_f0;
  bf16* xh = xsel ? s_xh1 : s_xh0;
  bf16* xl = xsel ? s_xl1 : s_xl0;
  float4 r = *(const float4*)(x + (size_t)row*CC + t*4);
  float o0 = (v.x-mu)*rs*g.x + b.x + r.x;
  float o1 = (v.y-mu)*rs*g.y + b.y + r.y;
  float o2 = (v.z-mu)*rs*g.z + b.z + r.z;
  float o3 = (v.w-mu)*rs*g.w + b.w + r.w;
  *(float4*)(x + (size_t)row*CC + t*4) = make_float4(o0,o1,o2,o3);
  split_store4(xh, xl, (size_t)row*CC + t*4, o0, o1, o2, o3);
}

__global__ __launch_bounds__(256)
void cat_copy(int xsel)
{
  const float* x = xsel ? g_f1 : g_f0;
  int i = blockIdx.x*256 + threadIdx.x;
  int row = i >> 7, c4 = i & 127;
  float4 v = *(const float4*)(x + (size_t)row*CC + c4*4);
  split_store4(s_ch, s_cl, (size_t)row*C2 + c4*4, v.x, v.y, v.z, v.w);
}

__global__ __launch_bounds__(256)
void copy_in(const float* __restrict__ f0, const float* __restrict__ f1)
{
  size_t i = (size_t)blockIdx.x*256 + threadIdx.x;
  float4 a = ((const float4*)f0)[i];
  float4 b = ((const float4*)f1)[i];
  ((float4*)g_f0)[i] = a;
  ((float4*)g_f1)[i] = b;
  split_store4(s_xh0, s_xl0, i*4, a.x, a.y, a.z, a.w);
  split_store4(s_xh1, s_xl1, i*4, b.x, b.y, b.z, b.w);
}

__global__ __launch_bounds__(256)
void copy_out(float* __restrict__ out)
{
  size_t i = (size_t)blockIdx.x*256 + threadIdx.x;
  ((float4*)out)[i]          = ((const float4*)g_f0)[i];
  ((float4*)out)[i + ELEMS4] = ((const float4*)g_f1)[i];
}

// ---------------- host-side layer driver ----------------
static void enc_layer(int xsel, int ssel, int layer,
                      const float* gg1, const float* bb1,
                      const float* gg2, const float* bb2)
{
  dim3 blk(256);
  dim3 g512(4, 128);
  dim3 g1024(8, 128);
  mma_gemm<1><<<g512, blk, MMA_SMEM>>>(xsel, 0, layer, 0, CC, CC);    // Q -> g_q
  mma_gemm<1><<<g512, blk, MMA_SMEM>>>(ssel, 1, layer, 1, CC, CC);    // K -> g_k
  mma_gemm<2><<<g512, blk, MMA_SMEM>>>(ssel, 2, layer, 2, CC, CC);    // V -> g_v
  kv_partial<<<dim3(SPLIT, NB*HH), blk>>>();
  kv_reduce<<<512, 256>>>();
  msg_kernel<<<dim3(LSEQ/64, NB*HH), blk>>>();                        // -> msg hi/lo
  mma_gemm<0><<<g512, blk, MMA_SMEM>>>(2, 3, layer, 3, CC, CC);       // msg@Wm -> g_m
  cat_copy<<<ELEMS4/256, blk>>>(xsel);                                // cat[:, :C] = x
  ln_to_cat<<<ROWS, 128>>>(gg1, bb1);                                 // cat[:, C:] = LN1
  mma_gemm<3><<<g1024, blk, MMA_SMEM>>>(3, 4, layer, 0, C2, C2);      // relu(cat@W1) -> t hi/lo
  mma_gemm<0><<<g512, blk, MMA_SMEM>>>(4, 5, layer, 1, CC, C2);       // t@W2 -> g_k
  ln_res<<<ROWS, 128>>>(xsel, gg2, bb2);                              // x += LN2(.)
}

extern "C" void kernel_launch(void* const* d_in, const int* in_sizes, int n_in,
                              void* d_out, int out_size)
{
  (void)in_sizes; (void)n_in; (void)out_size;
  const float* feat0 = (const float*)d_in[0];
  const float* feat1 = (const float*)d_in[1];
  const float* Wq = (const float*)d_in[2];
  const float* Wk = (const float*)d_in[3];
  const float* Wv = (const float*)d_in[4];
  const float* Wm = (const float*)d_in[5];
  const float* W1 = (const float*)d_in[6];
  const float* W2 = (const float*)d_in[7];
  const float* g1 = (const float*)d_in[8];
  const float* b1 = (const float*)d_in[9];
  const float* g2 = (const float*)d_in[10];
  const float* b2 = (const float*)d_in[11];

  cudaFuncSetAttribute(mma_gemm<0>, cudaFuncAttributeMaxDynamicSharedMemorySize, MMA_SMEM);
  cudaFuncSetAttribute(mma_gemm<1>, cudaFuncAttributeMaxDynamicSharedMemorySize, MMA_SMEM);
  cudaFuncSetAttribute(mma_gemm<2>, cudaFuncAttributeMaxDynamicSharedMemorySize, MMA_SMEM);
  cudaFuncSetAttribute(mma_gemm<3>, cudaFuncAttributeMaxDynamicSharedMemorySize, MMA_SMEM);

  dim3 wblk(32, 8);
  wprep<<<dim3(CC/32, CC/32, NLAYERS), wblk>>>(Wq, 0, CC, CC);
  wprep<<<dim3(CC/32, CC/32, NLAYERS), wblk>>>(Wk, 1, CC, CC);
  wprep<<<dim3(CC/32, CC/32, NLAYERS), wblk>>>(Wv, 2, CC, CC);
  wprep<<<dim3(CC/32, CC/32, NLAYERS), wblk>>>(Wm, 3, CC, CC);
  wprep<<<dim3(C2/32, C2/32, NLAYERS), wblk>>>(W1, 4, C2, C2);
  wprep<<<dim3(CC/32, C2/32, NLAYERS), wblk>>>(W2, 5, C2, CC);

  copy_in<<<ELEMS4/256, 256>>>(feat0, feat1);

  for (int i = 0; i < NLAYERS; i++){
    const float* gg1 = g1 + (size_t)i*CC;
    const float* bb1 = b1 + (size_t)i*CC;
    const float* gg2 = g2 + (size_t)i*CC;
    const float* bb2 = b2 + (size_t)i*CC;
    if ((i & 1) == 0){  // self
      enc_layer(0, 0, i, gg1, bb1, gg2, bb2);
      enc_layer(1, 1, i, gg1, bb1, gg2, bb2);
    } else {            // cross (sequential: feat1 sees updated feat0)
      enc_layer(0, 1, i, gg1, bb1, gg2, bb2);
      enc_layer(1, 0, i, gg1, bb1, gg2, bb2);
    }
  }

  copy_out<<<ELEMS4/256, 256>>>((float*)d_out);
}

// round 6
// speedup vs baseline: 3.9198x; 1.3272x over previous
#include <cuda_runtime.h>
#include <cuda_fp16.h>
#include <math.h>
#include <stdint.h>

#define NB 4
#define LSEQ 4096
#define CC 512
#define C2 1024
#define HH 8
#define DD 64
#define ROWS (NB*LSEQ)          // 16384
#define SPLIT 16
#define SCHUNK (LSEQ/SPLIT)     // 256
#define NLAYERS 12
#define ELEMS (ROWS*CC)         // 8388608
#define ELEMS4 (ELEMS/4)

typedef __half h16;

// ---------------- device globals (no allocation) ----------------
__device__ float g_f0[ELEMS], g_f1[ELEMS];
__device__ float g_q[ELEMS], g_k[ELEMS], g_v[ELEMS], g_m[ELEMS];
__device__ float g_kvp[SPLIT*NB*HH*DD*DD];
__device__ float g_ksp[SPLIT*NB*HH*DD];
__device__ float g_kv[NB*HH*DD*DD];
__device__ float g_ksum[NB*HH*DD];

// fp16 hi/lo activation shadows
__device__ h16 s_xh0[ELEMS], s_xl0[ELEMS], s_xh1[ELEMS], s_xl1[ELEMS];
__device__ h16 s_mh[ELEMS],  s_ml[ELEMS];
__device__ h16 s_ch0[ROWS*C2], s_cl0[ROWS*C2];
__device__ h16 s_ch1[ROWS*C2], s_cl1[ROWS*C2];
__device__ h16 s_th[ROWS*C2], s_tl[ROWS*C2];

// transposed fp16 weights: [N rows][K cols], per layer (hi only)
__device__ h16 w_q[NLAYERS*CC*CC];
__device__ h16 w_k[NLAYERS*CC*CC];
__device__ h16 w_v[NLAYERS*CC*CC];
__device__ h16 w_m[NLAYERS*CC*CC];
__device__ h16 w_1[NLAYERS*C2*C2];
__device__ h16 w_2[NLAYERS*CC*C2];

// ---------------- helpers ----------------
__device__ __forceinline__ uint32_t s2u(const void* p){
  uint32_t a;
  asm("{ .reg .u64 t; cvta.to.shared.u64 t, %1; cvt.u32.u64 %0, t; }" : "=r"(a) : "l"(p));
  return a;
}

__device__ __forceinline__ void hsplit_store4(h16* H, h16* L, size_t idx,
                                              float a, float b, float c, float d){
  h16 h0=__float2half(a), h1=__float2half(b), h2=__float2half(c), h3=__float2half(d);
  h16 l0=__float2half(a-__half2float(h0));
  h16 l1=__float2half(b-__half2float(h1));
  h16 l2=__float2half(c-__half2float(h2));
  h16 l3=__float2half(d-__half2float(h3));
  *(ushort4*)(H+idx) = make_ushort4(__half_as_ushort(h0), __half_as_ushort(h1),
                                    __half_as_ushort(h2), __half_as_ushort(h3));
  *(ushort4*)(L+idx) = make_ushort4(__half_as_ushort(l0), __half_as_ushort(l1),
                                    __half_as_ushort(l2), __half_as_ushort(l3));
}

__device__ __forceinline__ void hsplit_store2(h16* H, h16* L, size_t idx, float a, float b){
  h16 h0=__float2half(a), h1=__float2half(b);
  h16 l0=__float2half(a-__half2float(h0));
  h16 l1=__float2half(b-__half2float(h1));
  *(ushort2*)(H+idx) = make_ushort2(__half_as_ushort(h0), __half_as_ushort(h1));
  *(ushort2*)(L+idx) = make_ushort2(__half_as_ushort(l0), __half_as_ushort(l1));
}

__device__ __forceinline__ void cpasync16(uint32_t dst, const void* src){
  asm volatile("cp.async.cg.shared.global [%0], [%1], 16;" :: "r"(dst), "l"(src));
}

__device__ __forceinline__ void ldsm4(uint32_t* r, uint32_t addr){
  asm volatile("ldmatrix.sync.aligned.m8n8.x4.shared.b16 {%0,%1,%2,%3}, [%4];"
    : "=r"(r[0]),"=r"(r[1]),"=r"(r[2]),"=r"(r[3]) : "r"(addr));
}

__device__ __forceinline__ void mma16816(float* d, const uint32_t* a, const uint32_t* b){
  asm volatile("mma.sync.aligned.m16n8k16.row.col.f32.f16.f16.f32 "
    "{%0,%1,%2,%3},{%4,%5,%6,%7},{%8,%9},{%0,%1,%2,%3};"
    : "+f"(d[0]),"+f"(d[1]),"+f"(d[2]),"+f"(d[3])
    : "r"(a[0]),"r"(a[1]),"r"(a[2]),"r"(a[3]), "r"(b[0]),"r"(b[1]));
}

// swizzled byte offset within an 8KB tile (128 rows x 32 halves; 2 rows per 128B physrow)
__device__ __forceinline__ uint32_t swoff(int row, int c){
  int pr = row >> 1;
  int ch = ((row & 1)*4 + c) ^ (pr & 7);
  return (uint32_t)(pr*128 + ch*16);
}

// ---------------- operand selectors ----------------
// A: 0=x0, 1=x1, 2=msg, 3=cat0, 4=cat1, 5=t
__device__ __forceinline__ void apair(int s, const h16*& h, const h16*& l){
  switch(s){
    case 0: h=s_xh0; l=s_xl0; break;
    case 1: h=s_xh1; l=s_xl1; break;
    case 2: h=s_mh;  l=s_ml;  break;
    case 3: h=s_ch0; l=s_cl0; break;
    case 4: h=s_ch1; l=s_cl1; break;
    default:h=s_th;  l=s_tl;  break;
  }
}
__device__ __forceinline__ const h16* bsel(int s, int layer){
  switch(s){
    case 0: return w_q + (size_t)layer*CC*CC;
    case 1: return w_k + (size_t)layer*CC*CC;
    case 2: return w_v + (size_t)layer*CC*CC;
    case 3: return w_m + (size_t)layer*CC*CC;
    case 4: return w_1 + (size_t)layer*C2*C2;
    default:return w_2 + (size_t)layer*CC*C2;
  }
}
__device__ __forceinline__ float* cbuf(int s){
  switch(s){ case 0: return g_q; case 1: return g_k; case 2: return g_v; default: return g_m; }
}

// ---------------- split-fp16 GEMM via mma.sync ----------------
// C[M,N] = epi( (Ahi+Alo)[M,K] @ B^T[N,K] ), 128x128x32 CTA tile, 4-stage cp.async.
// EPI: 0 none->fp32, 1 elu+1->fp32, 3 relu->fp16 hi/lo (t buffers)
#define NSTG 4
#define STG_BYTES 24576
#define MMA_SMEM (NSTG*STG_BYTES)

template<int EPI>
__global__ __launch_bounds__(256)
void mma_gemm(int Asel, int Bsel, int layer, int Csel, int N, int K)
{
  extern __shared__ char smc[];
  const uint32_t sb = s2u(smc);

  const h16 *Ah,*Al;
  apair(Asel, Ah, Al);
  const h16* Bh = bsel(Bsel, layer);

  const int t = threadIdx.x, lane = t & 31, wid = t >> 5;
  const int wm = wid & 1, wn = wid >> 1;       // warp tile 64x32
  const int bm = blockIdx.y*128, bn = blockIdx.x*128;
  const int nc = K >> 5;

  const h16* gsrc[3];
  gsrc[0] = Ah + (size_t)bm*K;
  gsrc[1] = Al + (size_t)bm*K;
  gsrc[2] = Bh + (size_t)bn*K;

  const int lr0 = t >> 2, lc0 = t & 3;
  const int lm = lane >> 3, lrr = lane & 7;

  float acc[4][4][4];
#pragma unroll
  for (int i=0;i<4;i++)
#pragma unroll
    for (int j=0;j<4;j++)
#pragma unroll
      for (int q=0;q<4;q++) acc[i][j][q] = 0.f;

#define LOAD_STAGE(stg, ck) do {                                              \
    uint32_t base_ = sb + (stg)*STG_BYTES;                                    \
    int k0_ = (ck)*32;                                                        \
    _Pragma("unroll")                                                         \
    for (int tl_=0; tl_<3; tl_++){                                            \
      uint32_t tb_ = base_ + tl_*8192;                                        \
      const char* g_ = (const char*)(gsrc[tl_] + k0_);                        \
      cpasync16(tb_ + swoff(lr0,    lc0), g_ + ((size_t)lr0   *K + lc0*8)*2); \
      cpasync16(tb_ + swoff(lr0+64, lc0), g_ + ((size_t)(lr0+64)*K + lc0*8)*2);\
    }                                                                         \
    asm volatile("cp.async.commit_group;");                                   \
  } while(0)

  LOAD_STAGE(0, 0);
  LOAD_STAGE(1, 1);
  LOAD_STAGE(2, 2);            // nc >= 16 always

  for (int c = 0; c < nc; c++){
    if (c + 3 < nc) LOAD_STAGE((c+3)%NSTG, c+3);
    int rem = nc - 1 - c;
    if (rem >= 3)      asm volatile("cp.async.wait_group 3;" ::: "memory");
    else if (rem == 2) asm volatile("cp.async.wait_group 2;" ::: "memory");
    else if (rem == 1) asm volatile("cp.async.wait_group 1;" ::: "memory");
    else               asm volatile("cp.async.wait_group 0;" ::: "memory");
    __syncthreads();

    const uint32_t base = sb + (c%NSTG)*STG_BYTES;
#pragma unroll
    for (int k16 = 0; k16 < 2; k16++){
      uint32_t ah[4][4], al[4][4], bh[4][2];
#pragma unroll
      for (int mt = 0; mt < 4; mt++){
        int row = wm*64 + mt*16 + (lm&1)*8 + lrr;
        int ch  = k16*2 + (lm>>1);
        uint32_t o = swoff(row, ch);
        ldsm4(ah[mt], base + o);
        ldsm4(al[mt], base + 8192 + o);
      }
#pragma unroll
      for (int g = 0; g < 2; g++){
        int row = wn*32 + g*16 + (lm>>1)*8 + lrr;
        int ch  = k16*2 + (lm&1);
        uint32_t o = swoff(row, ch);
        uint32_t r4[4];
        ldsm4(r4, base + 16384 + o);
        bh[g*2][0]=r4[0]; bh[g*2][1]=r4[1]; bh[g*2+1][0]=r4[2]; bh[g*2+1][1]=r4[3];
      }
#pragma unroll
      for (int mt = 0; mt < 4; mt++)
#pragma unroll
        for (int nt = 0; nt < 4; nt++){
          mma16816(acc[mt][nt], ah[mt], bh[nt]);
          mma16816(acc[mt][nt], al[mt], bh[nt]);
        }
    }
    __syncthreads();
  }

  // ---------------- epilogue ----------------
  const int er = bm + wm*64 + (lane>>2);
  const int ec = bn + wn*32 + 2*(lane&3);
#pragma unroll
  for (int mt = 0; mt < 4; mt++){
#pragma unroll
    for (int nt = 0; nt < 4; nt++){
      int row = er + mt*16;
      int col = ec + nt*8;
      float v0 = acc[mt][nt][0], v1 = acc[mt][nt][1];
      float v2 = acc[mt][nt][2], v3 = acc[mt][nt][3];
      if (EPI == 1){
        v0 = v0 > 0.f ? v0 + 1.f : expf(v0);
        v1 = v1 > 0.f ? v1 + 1.f : expf(v1);
        v2 = v2 > 0.f ? v2 + 1.f : expf(v2);
        v3 = v3 > 0.f ? v3 + 1.f : expf(v3);
      } else if (EPI == 3){
        v0 = v0 > 0.f ? v0 : 0.f; v1 = v1 > 0.f ? v1 : 0.f;
        v2 = v2 > 0.f ? v2 : 0.f; v3 = v3 > 0.f ? v3 : 0.f;
      }
      if (EPI == 3){
        hsplit_store2(s_th, s_tl, (size_t)row*N + col, v0, v1);
        hsplit_store2(s_th, s_tl, (size_t)(row+8)*N + col, v2, v3);
      } else {
        float* C = cbuf(Csel);
        *(float2*)(C + (size_t)row*N + col)     = make_float2(v0, v1);
        *(float2*)(C + (size_t)(row+8)*N + col) = make_float2(v2, v3);
      }
    }
  }
}

// ---------------- weight prep: transpose + fp16 ----------------
__global__ __launch_bounds__(256)
void wprep(const float* __restrict__ W, int wsel, int K, int N)
{
  h16 *oh;
  switch(wsel){
    case 0: oh=w_q; break;
    case 1: oh=w_k; break;
    case 2: oh=w_v; break;
    case 3: oh=w_m; break;
    case 4: oh=w_1; break;
    default:oh=w_2; break;
  }
  const int l = blockIdx.z;
  const float* Wl = W + (size_t)l*K*N;
  oh += (size_t)l*(size_t)N*K;
  __shared__ float tile[32][33];
  const int k0 = blockIdx.y*32, n0 = blockIdx.x*32;
  const int tx = threadIdx.x, ty = threadIdx.y;
#pragma unroll
  for (int i = 0; i < 4; i++){
    int r = ty + i*8;
    tile[r][tx] = Wl[(size_t)(k0+r)*N + n0 + tx];
  }
  __syncthreads();
#pragma unroll
  for (int i = 0; i < 4; i++){
    int r = ty + i*8;
    oh[(size_t)(n0+r)*K + k0 + tx] = __float2half(tile[tx][r]);
  }
}

// ---------------- attention: KV split-K (deterministic) ----------------
__global__ __launch_bounds__(256)
void kv_partial()
{
  const int nh = blockIdx.y, part = blockIdx.x;
  const int n = nh >> 3, h = nh & 7;
  __shared__ float Ks[32][68];
  __shared__ float Vs[32][68];
  const int t = threadIdx.x;
  const int tx = t & 15, ty = t >> 4;
  const float* Kb = g_k + (size_t)n*LSEQ*CC + h*DD;
  const float* Vb = g_v + (size_t)n*LSEQ*CC + h*DD;
  float acc[4][4] = {};
  float ksum = 0.f;
  const int send = part*SCHUNK + SCHUNK;
  for (int s0 = part*SCHUNK; s0 < send; s0 += 32){
#pragma unroll
    for (int p = 0; p < 2; p++){
      int idx = t + p*256;
      int r = idx >> 4, c4 = (idx & 15) << 2;
      *(float4*)&Ks[r][c4] = *(const float4*)(Kb + (size_t)(s0+r)*CC + c4);
      *(float4*)&Vs[r][c4] = *(const float4*)(Vb + (size_t)(s0+r)*CC + c4);
    }
    __syncthreads();
    if (t < DD){
#pragma unroll
      for (int kk = 0; kk < 32; kk++) ksum += Ks[kk][t];
    }
#pragma unroll
    for (int kk = 0; kk < 32; kk++){
      float4 a = *(const float4*)&Ks[kk][ty*4];
      float4 b = *(const float4*)&Vs[kk][tx*4];
      float ar[4]={a.x,a.y,a.z,a.w}, br[4]={b.x,b.y,b.z,b.w};
#pragma unroll
      for (int i=0;i<4;i++)
#pragma unroll
        for (int j=0;j<4;j++) acc[i][j] = fmaf(ar[i],br[j],acc[i][j]);
    }
    __syncthreads();
  }
  float* dst = g_kvp + ((size_t)part*NB*HH + nh)*DD*DD;
#pragma unroll
  for (int i=0;i<4;i++)
    *(float4*)&dst[(ty*4+i)*DD + tx*4] =
        make_float4(acc[i][0],acc[i][1],acc[i][2],acc[i][3]);
  if (t < DD) g_ksp[(size_t)part*NB*HH*DD + nh*DD + t] = ksum;
}

__global__ __launch_bounds__(256)
void kv_reduce()
{
  int i = blockIdx.x*256 + threadIdx.x;
  if (i < NB*HH*DD*DD){
    float s = 0.f;
#pragma unroll
    for (int p=0;p<SPLIT;p++) s += g_kvp[(size_t)p*NB*HH*DD*DD + i];
    g_kv[i] = s;
  }
  if (i < NB*HH*DD){
    float s=0.f;
#pragma unroll
    for (int p=0;p<SPLIT;p++) s += g_ksp[p*NB*HH*DD + i];
    g_ksum[i] = s;
  }
}

// msg = (Q @ KVu) / (Q.Ksum+eps)  -> fp16 hi/lo pair  (S factors cancel exactly)
__global__ __launch_bounds__(256)
void msg_kernel()
{
  const int nh = blockIdx.y;
  const int n = nh >> 3, h = nh & 7;
  const int l0 = blockIdx.x * 64;
  __shared__ float Qs[64][68];
  __shared__ float KVs[64][68];
  __shared__ float ksm[64];
  __shared__ float zrow[64];
  const int t = threadIdx.x;
  const int tx = t & 15, ty = t >> 4;
  const float* Qb  = g_q  + (size_t)n*LSEQ*CC + h*DD;
  const float* KVb = g_kv + (size_t)nh*DD*DD;
#pragma unroll
  for (int p=0;p<4;p++){
    int idx = t + p*256;
    int r = idx >> 4, c4 = (idx & 15) << 2;
    float4 q = *(const float4*)(Qb + (size_t)(l0+r)*CC + c4);
    Qs[c4+0][r]=q.x; Qs[c4+1][r]=q.y; Qs[c4+2][r]=q.z; Qs[c4+3][r]=q.w;
    *(float4*)&KVs[r][c4] = *(const float4*)(KVb + r*DD + c4);
  }
  if (t < DD) ksm[t] = g_ksum[nh*DD + t];
  __syncthreads();
  if (t < DD){
    float dn = 0.f;
#pragma unroll
    for (int d=0; d<DD; d++) dn = fmaf(Qs[d][t], ksm[d], dn);
    zrow[t] = 1.0f / (dn + 1e-6f);
  }
  __syncthreads();
  float acc[4][4] = {};
#pragma unroll
  for (int kk=0; kk<DD; kk++){
    float4 a = *(const float4*)&Qs[kk][ty*4];
    float4 b = *(const float4*)&KVs[kk][tx*4];
    float ar[4]={a.x,a.y,a.z,a.w}, br[4]={b.x,b.y,b.z,b.w};
#pragma unroll
    for (int i=0;i<4;i++)
#pragma unroll
      for (int j=0;j<4;j++) acc[i][j] = fmaf(ar[i],br[j],acc[i][j]);
  }
#pragma unroll
  for (int i=0;i<4;i++){
    int m = ty*4+i;
    float z = zrow[m];
    size_t base = ((size_t)(n*LSEQ + l0 + m))*CC + h*DD + tx*4;
    hsplit_store4(s_mh, s_ml, base, acc[i][0]*z, acc[i][1]*z, acc[i][2]*z, acc[i][3]*z);
  }
}

// ---------------- LN kernels ----------------
__device__ __forceinline__ void ln_core(const float4& v, int t, float& mu, float& rs)
{
  float s  = v.x+v.y+v.z+v.w;
  float s2 = v.x*v.x + v.y*v.y + v.z*v.z + v.w*v.w;
  __shared__ float sh[8];
#pragma unroll
  for (int o=16;o>0;o>>=1){
    s  += __shfl_xor_sync(0xffffffffu, s, o);
    s2 += __shfl_xor_sync(0xffffffffu, s2, o);
  }
  if ((t & 31) == 0){ sh[t>>5] = s; sh[4 + (t>>5)] = s2; }
  __syncthreads();
  s  = sh[0]+sh[1]+sh[2]+sh[3];
  s2 = sh[4]+sh[5]+sh[6]+sh[7];
  mu = s * (1.0f/CC);
  float var = s2 * (1.0f/CC) - mu*mu;
  rs = rsqrtf(var + 1e-5f);
}

// LN(g_m) -> cat{xsel}[:, 512:1024] fp16 hi/lo
__global__ __launch_bounds__(128)
void ln_to_cat(int xsel, const float* __restrict__ gamma, const float* __restrict__ beta)
{
  const int row = blockIdx.x;
  const int t = threadIdx.x;
  float4 v = *(const float4*)(g_m + (size_t)row*CC + t*4);
  float mu, rs;
  ln_core(v, t, mu, rs);
  float4 g = *(const float4*)(gamma + t*4);
  float4 b = *(const float4*)(beta + t*4);
  float o0 = (v.x-mu)*rs*g.x + b.x;
  float o1 = (v.y-mu)*rs*g.y + b.y;
  float o2 = (v.z-mu)*rs*g.z + b.z;
  float o3 = (v.w-mu)*rs*g.w + b.w;
  h16* ch = xsel ? s_ch1 : s_ch0;
  h16* cl = xsel ? s_cl1 : s_cl0;
  hsplit_store4(ch, cl, (size_t)row*C2 + CC + t*4, o0, o1, o2, o3);
}

// x = x + LN(g_k); writes fp32 x, its fp16 shadow, and cat{xsel} x-half
__global__ __launch_bounds__(128)
void ln_res(int xsel, const float* __restrict__ gamma, const float* __restrict__ beta)
{
  const int row = blockIdx.x;
  const int t = threadIdx.x;
  float4 v = *(const float4*)(g_k + (size_t)row*CC + t*4);
  float mu, rs;
  ln_core(v, t, mu, rs);
  float4 g = *(const float4*)(gamma + t*4);
  float4 b = *(const float4*)(beta + t*4);
  float* x = xsel ? g_f1 : g_f0;
  h16* xh = xsel ? s_xh1 : s_xh0;
  h16* xl = xsel ? s_xl1 : s_xl0;
  h16* ch = xsel ? s_ch1 : s_ch0;
  h16* cl = xsel ? s_cl1 : s_cl0;
  float4 r = *(const float4*)(x + (size_t)row*CC + t*4);
  float o0 = (v.x-mu)*rs*g.x + b.x + r.x;
  float o1 = (v.y-mu)*rs*g.y + b.y + r.y;
  float o2 = (v.z-mu)*rs*g.z + b.z + r.z;
  float o3 = (v.w-mu)*rs*g.w + b.w + r.w;
  *(float4*)(x + (size_t)row*CC + t*4) = make_float4(o0,o1,o2,o3);
  hsplit_store4(xh, xl, (size_t)row*CC + t*4, o0, o1, o2, o3);
  hsplit_store4(ch, cl, (size_t)row*C2 + t*4, o0, o1, o2, o3);
}

__global__ __launch_bounds__(256)
void copy_in(const float* __restrict__ f0, const float* __restrict__ f1)
{
  size_t i = (size_t)blockIdx.x*256 + threadIdx.x;
  float4 a = ((const float4*)f0)[i];
  float4 b = ((const float4*)f1)[i];
  ((float4*)g_f0)[i] = a;
  ((float4*)g_f1)[i] = b;
  size_t row = i >> 7, c4 = i & 127;
  hsplit_store4(s_xh0, s_xl0, i*4, a.x, a.y, a.z, a.w);
  hsplit_store4(s_xh1, s_xl1, i*4, b.x, b.y, b.z, b.w);
  hsplit_store4(s_ch0, s_cl0, row*C2 + c4*4, a.x, a.y, a.z, a.w);
  hsplit_store4(s_ch1, s_cl1, row*C2 + c4*4, b.x, b.y, b.z, b.w);
}

__global__ __launch_bounds__(256)
void copy_out(float* __restrict__ out)
{
  size_t i = (size_t)blockIdx.x*256 + threadIdx.x;
  ((float4*)out)[i]          = ((const float4*)g_f0)[i];
  ((float4*)out)[i + ELEMS4] = ((const float4*)g_f1)[i];
}

// ---------------- host-side layer driver ----------------
static void enc_layer(int xsel, int ssel, int layer,
                      const float* gg1, const float* bb1,
                      const float* gg2, const float* bb2)
{
  dim3 blk(256);
  dim3 g512(4, 128);
  dim3 g1024(8, 128);
  mma_gemm<1><<<g512, blk, MMA_SMEM>>>(xsel, 0, layer, 0, CC, CC);    // Q -> g_q
  mma_gemm<1><<<g512, blk, MMA_SMEM>>>(ssel, 1, layer, 1, CC, CC);    // K -> g_k
  mma_gemm<0><<<g512, blk, MMA_SMEM>>>(ssel, 2, layer, 2, CC, CC);    // V (unscaled) -> g_v
  kv_partial<<<dim3(SPLIT, NB*HH), blk>>>();
  kv_reduce<<<512, 256>>>();
  msg_kernel<<<dim3(LSEQ/64, NB*HH), blk>>>();                        // -> msg hi/lo
  mma_gemm<0><<<g512, blk, MMA_SMEM>>>(2, 3, layer, 3, CC, CC);       // msg@Wm -> g_m
  ln_to_cat<<<ROWS, 128>>>(xsel, gg1, bb1);                           // cat{x}[:, C:] = LN1
  mma_gemm<3><<<g1024, blk, MMA_SMEM>>>(3+xsel, 4, layer, 0, C2, C2); // relu(cat@W1) -> t
  mma_gemm<0><<<g512, blk, MMA_SMEM>>>(5, 5, layer, 1, CC, C2);       // t@W2 -> g_k
  ln_res<<<ROWS, 128>>>(xsel, gg2, bb2);                              // x += LN2(.)
}

extern "C" void kernel_launch(void* const* d_in, const int* in_sizes, int n_in,
                              void* d_out, int out_size)
{
  (void)in_sizes; (void)n_in; (void)out_size;
  const float* feat0 = (const float*)d_in[0];
  const float* feat1 = (const float*)d_in[1];
  const float* Wq = (const float*)d_in[2];
  const float* Wk = (const float*)d_in[3];
  const float* Wv = (const float*)d_in[4];
  const float* Wm = (const float*)d_in[5];
  const float* W1 = (const float*)d_in[6];
  const float* W2 = (const float*)d_in[7];
  const float* g1 = (const float*)d_in[8];
  const float* b1 = (const float*)d_in[9];
  const float* g2 = (const float*)d_in[10];
  const float* b2 = (const float*)d_in[11];

  cudaFuncSetAttribute(mma_gemm<0>, cudaFuncAttributeMaxDynamicSharedMemorySize, MMA_SMEM);
  cudaFuncSetAttribute(mma_gemm<1>, cudaFuncAttributeMaxDynamicSharedMemorySize, MMA_SMEM);
  cudaFuncSetAttribute(mma_gemm<3>, cudaFuncAttributeMaxDynamicSharedMemorySize, MMA_SMEM);

  dim3 wblk(32, 8);
  wprep<<<dim3(CC/32, CC/32, NLAYERS), wblk>>>(Wq, 0, CC, CC);
  wprep<<<dim3(CC/32, CC/32, NLAYERS), wblk>>>(Wk, 1, CC, CC);
  wprep<<<dim3(CC/32, CC/32, NLAYERS), wblk>>>(Wv, 2, CC, CC);
  wprep<<<dim3(CC/32, CC/32, NLAYERS), wblk>>>(Wm, 3, CC, CC);
  wprep<<<dim3(C2/32, C2/32, NLAYERS), wblk>>>(W1, 4, C2, C2);
  wprep<<<dim3(CC/32, C2/32, NLAYERS), wblk>>>(W2, 5, C2, CC);

  copy_in<<<ELEMS4/256, 256>>>(feat0, feat1);

  for (int i = 0; i < NLAYERS; i++){
    const float* gg1 = g1 + (size_t)i*CC;
    const float* bb1 = b1 + (size_t)i*CC;
    const float* gg2 = g2 + (size_t)i*CC;
    const float* bb2 = b2 + (size_t)i*CC;
    if ((i & 1) == 0){  // self
      enc_layer(0, 0, i, gg1, bb1, gg2, bb2);
      enc_layer(1, 1, i, gg1, bb1, gg2, bb2);
    } else {            // cross (sequential: feat1 sees updated feat0)
      enc_layer(0, 1, i, gg1, bb1, gg2, bb2);
      enc_layer(1, 0, i, gg1, bb1, gg2, bb2);
    }
  }

  copy_out<<<ELEMS4/256, 256>>>((float*)d_out);
}